// round 7
// baseline (speedup 1.0000x reference)
#include <cuda_runtime.h>

#define NU 200000
#define NI 100000
#define NN 300000
#define EE 9600000
#define SCAN_CHUNK 8192
#define NB_SCAN ((NN + SCAN_CHUNK - 1) / SCAN_CHUNK)   // 37 blocks

// ---- scratch (static device globals; zero-initialized at module load) ----
__device__ int    g_cnt[NN];           // re-zeroed by k_scan each replay
__device__ int    g_rowptr[NN + 1];
__device__ int    g_chain[NB_SCAN];    // chained-scan handoff; self-resetting
__device__ int    g_rank[EE];          // intra-row rank of each edge
__device__ int2   g_edge[EE];          // packed {col, val_bits}, row-sorted
__device__ uint4  g_h1[NN * 4];        // x1 in bf16 (32 bf16 = 64 B per row)
__device__ uint4  g_h2[NN * 4];        // x2 in bf16

// ---------------- packed-math helpers ----------------
__device__ __forceinline__ unsigned long long ffma2(unsigned long long a,
                                                    unsigned long long b,
                                                    unsigned long long c) {
    unsigned long long d;
    asm("fma.rn.f32x2 %0, %1, %2, %3;" : "=l"(d) : "l"(a), "l"(b), "l"(c));
    return d;
}
__device__ __forceinline__ unsigned long long addf2(unsigned long long a,
                                                    unsigned long long b) {
    unsigned long long d;
    asm("add.rn.f32x2 %0, %1, %2;" : "=l"(d) : "l"(a), "l"(b));
    return d;
}
__device__ __forceinline__ unsigned long long packrr(unsigned int lo, unsigned int hi) {
    unsigned long long d;
    asm("mov.b64 %0, {%1, %2};" : "=l"(d) : "r"(lo), "r"(hi));
    return d;
}
__device__ __forceinline__ void unpackff(unsigned long long d, float& lo, float& hi) {
    asm("mov.b64 {%0, %1}, %2;" : "=f"(lo), "=f"(hi) : "l"(d));
}
// bf16x2 word -> packed f32x2 {lo_feature, hi_feature}; pure ALU (no cvt path)
__device__ __forceinline__ unsigned long long bfup(unsigned int h) {
    return packrr(h << 16, h & 0xFFFF0000u);
}
// two f32 -> bf16x2 word, round-to-nearest; feature f0 in low half
__device__ __forceinline__ unsigned int pkbf(float f1, float f0) {
    unsigned int r;
    asm("cvt.rn.bf16x2.f32 %0, %1, %2;" : "=r"(r) : "f"(f1), "f"(f0));
    return r;
}
__device__ __forceinline__ unsigned long long shfl64(unsigned long long v, int o) {
    return __shfl_down_sync(0xffffffffu, v, o);
}

// ---------------- CSR build ----------------
__global__ void k_hist(const int* __restrict__ rows) {
    int e = blockIdx.x * blockDim.x + threadIdx.x;
    if (e < EE) g_rank[e] = atomicAdd(&g_cnt[rows[e]], 1);
}

// single-pass chained scan: block b handles rows [b*8192, (b+1)*8192)
__global__ void __launch_bounds__(1024) k_scan() {
    __shared__ int sh[1024];
    __shared__ int s_base;
    int tid = threadIdx.x;
    int b   = blockIdx.x;
    int base = b * SCAN_CHUNK + tid * 8;
    int v[8];
    int run = 0;
#pragma unroll
    for (int i = 0; i < 8; i++) {
        int idx = base + i;
        int c = 0;
        if (idx < NN) { c = g_cnt[idx]; g_cnt[idx] = 0; }  // consume + re-zero for replay
        v[i] = run;
        run += c;
    }
    sh[tid] = run;
    __syncthreads();
    for (int off = 1; off < 1024; off <<= 1) {
        int t = (tid >= off) ? sh[tid - off] : 0;
        __syncthreads();
        sh[tid] += t;
        __syncthreads();
    }
    int pre   = sh[tid] - run;   // exclusive prefix within block
    int total = sh[1023];
    if (tid == 0) {
        int myb = 0;
        if (b > 0) {
            volatile int* ch = g_chain;
            int t;
            do { t = ch[b - 1]; } while (t == 0);
            __threadfence();
            myb = t & 0x3FFFFFFF;
            ch[b - 1] = 0;                         // reset for next replay
        }
        s_base = myb;
        if (b < NB_SCAN - 1) {
            __threadfence();
            *((volatile int*)&g_chain[b]) = 0x40000000 | (myb + total);
        }
    }
    __syncthreads();
    int gbase = s_base + pre;
#pragma unroll
    for (int i = 0; i < 8; i++) {
        int idx = base + i;
        if (idx < NN) g_rowptr[idx] = gbase + v[i];
    }
    if (b == NB_SCAN - 1 && tid == 1023) g_rowptr[NN] = EE;
}

// atomic-free scatter: pos = rowptr[row] + rank
__global__ void k_scatter(const int* __restrict__ rows, const int* __restrict__ cols,
                          const float* __restrict__ vals) {
    int e = blockIdx.x * blockDim.x + threadIdx.x;
    if (e < EE) {
        int p = g_rowptr[rows[e]] + g_rank[e];
        g_edge[p] = make_int2(cols[e], __float_as_int(vals[e]));
    }
}

// ---------------- layer 0: f32 gather from uw/iw, FFMA2, writes bf16 x1 + out ----------------
__device__ __forceinline__ const uint4* gp0(const uint4* __restrict__ uw,
                                            const uint4* __restrict__ iw, int c) {
    return (c < NU) ? (uw + (size_t)c * 8) : (iw + (size_t)(c - NU) * 8);
}

__global__ void __launch_bounds__(256) k_spmm0(const uint4* __restrict__ uw,
                                               const uint4* __restrict__ iw,
                                               float4* __restrict__ out4) {
    int w = (blockIdx.x * 256 + threadIdx.x) >> 5;
    if (w >= NN) return;
    int lane = threadIdx.x & 31;
    int sub  = lane >> 3;   // 4 edges per group
    int q    = lane & 7;    // float4 chunk of the 128-B row

    const int2* __restrict__ ed = g_edge;
    int s = g_rowptr[w];
    int e = g_rowptr[w + 1];

    unsigned long long acc0 = 0, acc1 = 0;   // 4 f32 accumulators, packed
    int j = s;
    for (; j + 16 <= e; j += 16) {
        int2 e0 = ed[j + sub];
        int2 e1 = ed[j + 4 + sub];
        int2 e2 = ed[j + 8 + sub];
        int2 e3 = ed[j + 12 + sub];
        uint4 a0 = gp0(uw, iw, e0.x)[q];
        uint4 a1 = gp0(uw, iw, e1.x)[q];
        uint4 a2 = gp0(uw, iw, e2.x)[q];
        uint4 a3 = gp0(uw, iw, e3.x)[q];
        unsigned long long v0 = packrr(e0.y, e0.y);
        unsigned long long v1 = packrr(e1.y, e1.y);
        unsigned long long v2 = packrr(e2.y, e2.y);
        unsigned long long v3 = packrr(e3.y, e3.y);
        acc0 = ffma2(packrr(a0.x, a0.y), v0, acc0);
        acc1 = ffma2(packrr(a0.z, a0.w), v0, acc1);
        acc0 = ffma2(packrr(a1.x, a1.y), v1, acc0);
        acc1 = ffma2(packrr(a1.z, a1.w), v1, acc1);
        acc0 = ffma2(packrr(a2.x, a2.y), v2, acc0);
        acc1 = ffma2(packrr(a2.z, a2.w), v2, acc1);
        acc0 = ffma2(packrr(a3.x, a3.y), v3, acc0);
        acc1 = ffma2(packrr(a3.z, a3.w), v3, acc1);
    }
    for (; j < e; j += 4) {
        int je = j + sub;
        int c = 0;
        unsigned int vb = 0;
        if (je < e) { int2 t = ed[je]; c = t.x; vb = (unsigned int)t.y; }
        uint4 a = gp0(uw, iw, c)[q];
        unsigned long long v = packrr(vb, vb);
        acc0 = ffma2(packrr(a.x, a.y), v, acc0);
        acc1 = ffma2(packrr(a.z, a.w), v, acc1);
    }
#pragma unroll
    for (int o = 16; o >= 8; o >>= 1) {
        acc0 = addf2(acc0, shfl64(acc0, o));
        acc1 = addf2(acc1, shfl64(acc1, o));
    }
    if (lane < 8) {   // lane owns features [4*lane, 4*lane+4)
        float f0, f1, f2, f3;
        unpackff(acc0, f0, f1);
        unpackff(acc1, f2, f3);
        // bf16 row chunk of x1
        uint2 hb = make_uint2(pkbf(f1, f0), pkbf(f3, f2));
        reinterpret_cast<uint2*>(g_h1)[(size_t)w * 8 + lane] = hb;
        // out = x0 + x1
        size_t oi = (size_t)w * 8 + lane;
        const float4* x0p = (w < NU) ? reinterpret_cast<const float4*>(uw) + oi
                                     : reinterpret_cast<const float4*>(iw) + ((size_t)(w - NU) * 8 + lane);
        float4 x0 = *x0p;
        out4[oi] = make_float4(x0.x + f0, x0.y + f1, x0.z + f2, x0.w + f3);
    }
}

// ---------------- layers 1/2: bf16 gather, ALU unpack + FFMA2 ----------------
__device__ __forceinline__ void fma8b(unsigned long long* acc, uint4 h,
                                      unsigned long long vv) {
    acc[0] = ffma2(bfup(h.x), vv, acc[0]);
    acc[1] = ffma2(bfup(h.y), vv, acc[1]);
    acc[2] = ffma2(bfup(h.z), vv, acc[2]);
    acc[3] = ffma2(bfup(h.w), vv, acc[3]);
}

template <int L>
__global__ void __launch_bounds__(256) k_spmmb(float4* __restrict__ out4) {
    int w = (blockIdx.x * 256 + threadIdx.x) >> 5;
    if (w >= NN) return;
    int lane = threadIdx.x & 31;
    int sub  = lane >> 2;   // 8 edges per group
    int q    = lane & 3;    // uint4 chunk of the 64-B row

    const uint4* __restrict__ hx = (L == 1) ? g_h1 : g_h2;
    const int2*  __restrict__ ed = g_edge;

    int s = g_rowptr[w];
    int e = g_rowptr[w + 1];

    unsigned long long acc[4] = {0ull, 0ull, 0ull, 0ull};
    int j = s;
    for (; j + 32 <= e; j += 32) {
        int2 e0 = ed[j + sub];
        int2 e1 = ed[j + 8 + sub];
        int2 e2 = ed[j + 16 + sub];
        int2 e3 = ed[j + 24 + sub];
        uint4 h0 = hx[e0.x * 4 + q];
        uint4 h1 = hx[e1.x * 4 + q];
        uint4 h2 = hx[e2.x * 4 + q];
        uint4 h3 = hx[e3.x * 4 + q];
        fma8b(acc, h0, packrr(e0.y, e0.y));
        fma8b(acc, h1, packrr(e1.y, e1.y));
        fma8b(acc, h2, packrr(e2.y, e2.y));
        fma8b(acc, h3, packrr(e3.y, e3.y));
    }
    if (j + 16 <= e) {
        int2 e0 = ed[j + sub];
        int2 e1 = ed[j + 8 + sub];
        uint4 h0 = hx[e0.x * 4 + q];
        uint4 h1 = hx[e1.x * 4 + q];
        fma8b(acc, h0, packrr(e0.y, e0.y));
        fma8b(acc, h1, packrr(e1.y, e1.y));
        j += 16;
    }
    for (; j < e; j += 8) {
        int je = j + sub;
        int c = 0;
        unsigned int vb = 0;
        if (je < e) { int2 t = ed[je]; c = t.x; vb = (unsigned int)t.y; }
        uint4 h = hx[c * 4 + q];
        fma8b(acc, h, packrr(vb, vb));
    }
#pragma unroll
    for (int o = 16; o >= 4; o >>= 1) {
#pragma unroll
        for (int k = 0; k < 4; k++) acc[k] = addf2(acc[k], shfl64(acc[k], o));
    }

    if (lane < 4) {   // lane == q; owns features [8q, 8q+8)
        float f[8];
        unpackff(acc[0], f[0], f[1]);
        unpackff(acc[1], f[2], f[3]);
        unpackff(acc[2], f[4], f[5]);
        unpackff(acc[3], f[6], f[7]);
        size_t ob = (size_t)w * 8 + lane * 2;
        if (L == 1) {
            uint4 hb = make_uint4(pkbf(f[1], f[0]), pkbf(f[3], f[2]),
                                  pkbf(f[5], f[4]), pkbf(f[7], f[6]));
            g_h2[(size_t)w * 4 + lane] = hb;
            float4 t0 = out4[ob], t1 = out4[ob + 1];
            out4[ob]     = make_float4(t0.x + f[0], t0.y + f[1], t0.z + f[2], t0.w + f[3]);
            out4[ob + 1] = make_float4(t1.x + f[4], t1.y + f[5], t1.z + f[6], t1.w + f[7]);
        } else {
            float4 t0 = out4[ob], t1 = out4[ob + 1];
            out4[ob]     = make_float4((t0.x + f[0]) * 0.25f, (t0.y + f[1]) * 0.25f,
                                       (t0.z + f[2]) * 0.25f, (t0.w + f[3]) * 0.25f);
            out4[ob + 1] = make_float4((t1.x + f[4]) * 0.25f, (t1.y + f[5]) * 0.25f,
                                       (t1.z + f[6]) * 0.25f, (t1.w + f[7]) * 0.25f);
        }
    }
}

extern "C" void kernel_launch(void* const* d_in, const int* in_sizes, int n_in,
                              void* d_out, int out_size) {
    const int*   rows = (const int*)d_in[0];
    const int*   cols = (const int*)d_in[1];
    const float* vals = (const float*)d_in[2];
    const uint4* uw   = (const uint4*)d_in[3];
    const uint4* iw   = (const uint4*)d_in[4];
    float4*      out4 = (float4*)d_out;

    (void)in_sizes; (void)n_in; (void)out_size;

    k_hist   <<<(EE + 255) / 256, 256>>>(rows);
    k_scan   <<<NB_SCAN, 1024>>>();
    k_scatter<<<(EE + 255) / 256, 256>>>(rows, cols, vals);

    k_spmm0  <<<NN / 8, 256>>>(uw, iw, out4);   // 4th launch -> profiled
    k_spmmb<1><<<NN / 8, 256>>>(out4);
    k_spmmb<2><<<NN / 8, 256>>>(out4);
}

// round 8
// speedup vs baseline: 1.2976x; 1.2976x over previous
#include <cuda_runtime.h>

#define NU 200000
#define NI 100000
#define NN 300000
#define EE 9600000
#define SCAN_CHUNK 8192
#define NB_SCAN ((NN + SCAN_CHUNK - 1) / SCAN_CHUNK)   // 37 blocks

// ---- scratch (static device globals; zero-initialized at module load) ----
__device__ int    g_cnt[NN];           // re-zeroed by k_scan each replay
__device__ int    g_rowptr[NN + 1];
__device__ int    g_off[NN];
__device__ int    g_chain[NB_SCAN];    // chained-scan handoff; self-resetting
__device__ int2   g_edge[EE];          // packed {col, val_bits}, row-sorted
__device__ float4 g_x[NN * 8];         // x1 (f32), gathered by layer 1
__device__ float4 g_y[NN * 8];         // x2 (f32), gathered by layer 2

// ---------------- CSR build ----------------
__global__ void k_hist(const int* __restrict__ rows) {
    int e = blockIdx.x * blockDim.x + threadIdx.x;
    if (e < EE) atomicAdd(&g_cnt[rows[e]], 1);
}

// single-pass chained scan: block b handles rows [b*8192, (b+1)*8192)
__global__ void __launch_bounds__(1024) k_scan() {
    __shared__ int sh[1024];
    __shared__ int s_base;
    int tid = threadIdx.x;
    int b   = blockIdx.x;
    int base = b * SCAN_CHUNK + tid * 8;
    int v[8];
    int run = 0;
#pragma unroll
    for (int i = 0; i < 8; i++) {
        int idx = base + i;
        int c = 0;
        if (idx < NN) { c = g_cnt[idx]; g_cnt[idx] = 0; }  // consume + re-zero for replay
        v[i] = run;
        run += c;
    }
    sh[tid] = run;
    __syncthreads();
    for (int off = 1; off < 1024; off <<= 1) {
        int t = (tid >= off) ? sh[tid - off] : 0;
        __syncthreads();
        sh[tid] += t;
        __syncthreads();
    }
    int pre   = sh[tid] - run;   // exclusive prefix within block
    int total = sh[1023];
    if (tid == 0) {
        int myb = 0;
        if (b > 0) {
            volatile int* ch = g_chain;
            int t;
            do { t = ch[b - 1]; } while (t == 0);
            __threadfence();
            myb = t & 0x3FFFFFFF;
            ch[b - 1] = 0;                         // reset for next replay
        }
        s_base = myb;
        if (b < NB_SCAN - 1) {
            __threadfence();
            *((volatile int*)&g_chain[b]) = 0x40000000 | (myb + total);
        }
    }
    __syncthreads();
    int gbase = s_base + pre;
#pragma unroll
    for (int i = 0; i < 8; i++) {
        int idx = base + i;
        if (idx < NN) {
            int p = gbase + v[i];
            g_rowptr[idx] = p;
            g_off[idx]    = p;
        }
    }
    if (b == NB_SCAN - 1 && tid == 1023) g_rowptr[NN] = EE;
}

// atomic scatter: p = g_off[r]++ (R2 form; measured faster than rank-based)
__global__ void k_scatter(const int* __restrict__ rows, const int* __restrict__ cols,
                          const float* __restrict__ vals) {
    int e = blockIdx.x * blockDim.x + threadIdx.x;
    if (e < EE) {
        int r = rows[e];
        int p = atomicAdd(&g_off[r], 1);
        g_edge[p] = make_int2(cols[e], __float_as_int(vals[e]));
    }
}

// ---------------- SpMM: warp per row, scalar f32, fused epilogues ----------------
// L=0: gather uw/iw -> g_x = x1,  out = x0 + x1
// L=1: gather g_x   -> g_y = x2,  out += x2
// L=2: gather g_y   ->            out = (out + x3) * 0.25
__device__ __forceinline__ float4 gath0(const float4* __restrict__ uw,
                                        const float4* __restrict__ iw, int c, int q) {
    const float4* p = (c < NU) ? (uw + (size_t)c * 8) : (iw + (size_t)(c - NU) * 8);
    return p[q];
}

template <int L>
__global__ void __launch_bounds__(256) k_spmmf(const float4* __restrict__ uw,
                                               const float4* __restrict__ iw,
                                               float4* __restrict__ out4) {
    int w = (blockIdx.x * 256 + threadIdx.x) >> 5;
    if (w >= NN) return;
    int lane = threadIdx.x & 31;
    int sub  = lane >> 3;   // which of 4 edges in the group
    int q    = lane & 7;    // float4 chunk of the 128-B row

    const float4* __restrict__ x4 = (L == 1) ? g_x : g_y;  // L==0 unused
    const int2*   __restrict__ ed = g_edge;

    int s = g_rowptr[w];
    int e = g_rowptr[w + 1];

    float4 acc = make_float4(0.f, 0.f, 0.f, 0.f);
    int j = s;
    // main loop: 16 edges per iteration (4 gather groups in flight)
    for (; j + 16 <= e; j += 16) {
        int2 e0 = ed[j + sub];
        int2 e1 = ed[j + 4 + sub];
        int2 e2 = ed[j + 8 + sub];
        int2 e3 = ed[j + 12 + sub];
        float4 a0, a1, a2, a3;
        if (L == 0) {
            a0 = gath0(uw, iw, e0.x, q);
            a1 = gath0(uw, iw, e1.x, q);
            a2 = gath0(uw, iw, e2.x, q);
            a3 = gath0(uw, iw, e3.x, q);
        } else {
            a0 = x4[(size_t)e0.x * 8 + q];
            a1 = x4[(size_t)e1.x * 8 + q];
            a2 = x4[(size_t)e2.x * 8 + q];
            a3 = x4[(size_t)e3.x * 8 + q];
        }
        float v0 = __int_as_float(e0.y), v1 = __int_as_float(e1.y);
        float v2 = __int_as_float(e2.y), v3 = __int_as_float(e3.y);
        acc.x += v0 * a0.x + v1 * a1.x + v2 * a2.x + v3 * a3.x;
        acc.y += v0 * a0.y + v1 * a1.y + v2 * a2.y + v3 * a3.y;
        acc.z += v0 * a0.z + v1 * a1.z + v2 * a2.z + v3 * a3.z;
        acc.w += v0 * a0.w + v1 * a1.w + v2 * a2.w + v3 * a3.w;
    }
    // tail: groups of up to 4 edges, predicated
    for (; j < e; j += 4) {
        int je = j + sub;
        int c = 0;
        float v = 0.f;
        if (je < e) { int2 t = ed[je]; c = t.x; v = __int_as_float(t.y); }
        float4 a;
        if (L == 0) a = gath0(uw, iw, c, q);
        else        a = x4[(size_t)c * 8 + q];
        acc.x += v * a.x;
        acc.y += v * a.y;
        acc.z += v * a.z;
        acc.w += v * a.w;
    }
    // reduce across the 4 edge sub-groups (lanes sharing q)
#pragma unroll
    for (int o = 16; o >= 8; o >>= 1) {
        acc.x += __shfl_down_sync(0xffffffffu, acc.x, o);
        acc.y += __shfl_down_sync(0xffffffffu, acc.y, o);
        acc.z += __shfl_down_sync(0xffffffffu, acc.z, o);
        acc.w += __shfl_down_sync(0xffffffffu, acc.w, o);
    }

    if (lane < 8) {
        size_t oi = (size_t)w * 8 + lane;
        if (L == 0) {
            float4 x0 = (w < NU) ? uw[oi] : iw[(size_t)(w - NU) * 8 + lane];
            g_x[oi] = acc;
            out4[oi] = make_float4(x0.x + acc.x, x0.y + acc.y, x0.z + acc.z, x0.w + acc.w);
        } else if (L == 1) {
            float4 t = out4[oi];
            g_y[oi] = acc;
            out4[oi] = make_float4(t.x + acc.x, t.y + acc.y, t.z + acc.z, t.w + acc.w);
        } else {
            float4 t = out4[oi];
            out4[oi] = make_float4((t.x + acc.x) * 0.25f, (t.y + acc.y) * 0.25f,
                                   (t.z + acc.z) * 0.25f, (t.w + acc.w) * 0.25f);
        }
    }
}

extern "C" void kernel_launch(void* const* d_in, const int* in_sizes, int n_in,
                              void* d_out, int out_size) {
    const int*    rows = (const int*)d_in[0];
    const int*    cols = (const int*)d_in[1];
    const float*  vals = (const float*)d_in[2];
    const float4* uw   = (const float4*)d_in[3];
    const float4* iw   = (const float4*)d_in[4];
    float4*       out4 = (float4*)d_out;

    (void)in_sizes; (void)n_in; (void)out_size;

    k_hist    <<<(EE + 255) / 256, 256>>>(rows);
    k_scan    <<<NB_SCAN, 1024>>>();
    k_scatter <<<(EE + 255) / 256, 256>>>(rows, cols, vals);

    k_spmmf<0><<<NN / 8, 256>>>(uw, iw, out4);   // 4th launch -> profiled
    k_spmmf<1><<<NN / 8, 256>>>(uw, iw, out4);
    k_spmmf<2><<<NN / 8, 256>>>(uw, iw, out4);
}